// round 13
// baseline (speedup 1.0000x reference)
#include <cuda_runtime.h>
#include <cuda_bf16.h>
#include <stdint.h>
#include <math.h>
#include <float.h>

#define BB 8
#define CC 64
#define NN 2048
#define KK 32

// ---------------- scratch (device globals) ----------------
__device__ float g_gram[(size_t)BB * NN * NN];      // scores: 2*inner - xx[col]
__device__ __nv_bfloat16 g_xhi[BB * NN * CC];       // (B,N,64) bf16 hi, row-major
__device__ __nv_bfloat16 g_xlo[BB * NN * CC];       // bf16 lo residual
__device__ float g_qT[BB * NN * CC];
__device__ float g_kT[BB * NN * CC];
__device__ float g_vT[BB * NN * CC];
__device__ float g_xx[BB * NN];
__device__ int   g_idx[BB * NN * KK];
__device__ float g_attnT[BB * NN * CC];
__device__ float g_y1T[BB * NN * CC];
__device__ float g_y2T[BB * NN * CC];
__device__ float g_p1s[64 * 64], g_p1ss[64 * 64];
__device__ float g_p2s[64 * 512], g_p2ss[64 * 512];
__device__ float g_sc1[64], g_sh1[64], g_sc2[64], g_sh2[64];

// ---------------- helpers ----------------
__device__ __forceinline__ uint32_t smem_u32(const void* p) {
    uint32_t a;
    asm("{ .reg .u64 t; cvta.to.shared.u64 t, %1; cvt.u32.u64 %0, t; }" : "=r"(a) : "l"(p));
    return a;
}
#define SW128(off) ((off) ^ (((off) >> 3) & 0x70))

// ---------------- K1: projections + norms + bf16 hi/lo split ----------------
__global__ void proj_kernel(const float* __restrict__ x,
                            const float* __restrict__ Wq,
                            const float* __restrict__ Wk,
                            const float* __restrict__ Wv) {
    __shared__ float xs[64][33];
    __shared__ float os[32][65];
    int b = blockIdx.y;
    int n0 = blockIdx.x * 32;
    int t = threadIdx.x;
    const float* xb = x + (size_t)b * CC * NN;

    #pragma unroll
    for (int i = 0; i < 8; i++) {
        int e = t + i * 256;
        int c = e >> 5, j = e & 31;
        xs[c][j] = xb[c * NN + n0 + j];
    }
    __syncthreads();

    if (t < 32) {
        float s = 0.f;
        #pragma unroll
        for (int c = 0; c < 64; c++) { float v = xs[c][t]; s += v * v; }
        g_xx[b * NN + n0 + t] = s;
    }

    // bf16 hi/lo transposed write: (B,N,64)
    #pragma unroll
    for (int i = 0; i < 4; i++) {
        int e = t + i * 256;         // 0..1023
        int p = e >> 5;              // point 0..31
        int cp = e & 31;             // channel pair 0..31
        float v0 = xs[cp * 2][p], v1 = xs[cp * 2 + 1][p];
        __nv_bfloat16 h0 = __float2bfloat16(v0);
        __nv_bfloat16 h1 = __float2bfloat16(v1);
        __nv_bfloat16 l0 = __float2bfloat16(v0 - __bfloat162float(h0));
        __nv_bfloat16 l1 = __float2bfloat16(v1 - __bfloat162float(h1));
        size_t off = ((size_t)(b * NN + n0 + p)) * 64 + cp * 2;
        __nv_bfloat162 hh; hh.x = h0; hh.y = h1;
        __nv_bfloat162 ll; ll.x = l0; ll.y = l1;
        *(__nv_bfloat162*)(g_xhi + off) = hh;
        *(__nv_bfloat162*)(g_xlo + off) = ll;
    }

    int lane = t & 31;
    int w = t >> 5;
    const float* Ws[3] = {Wq, Wk, Wv};
    float* Os[3] = {g_qT, g_kT, g_vT};

    #pragma unroll
    for (int mtx = 0; mtx < 3; mtx++) {
        const float* W = Ws[mtx];
        #pragma unroll
        for (int p = 0; p < 8; p++) {
            int o = p * 8 + w;
            float s = 0.f;
            #pragma unroll
            for (int c = 0; c < 64; c++) s += W[o * 64 + c] * xs[c][lane];
            os[lane][o] = s;
        }
        __syncthreads();
        float* Ob = Os[mtx] + ((size_t)(b * NN + n0)) * 64;
        #pragma unroll
        for (int q = 0; q < 8; q++) {
            int e = t + q * 256;
            int pt = e >> 6, o = e & 63;
            Ob[pt * 64 + o] = os[pt][o];
        }
        __syncthreads();
    }
}

// ---------------- K2: Gram via mma.sync bf16 split (HMMA) ----------------
#define GSM_XX 0
#define GSM_AHI 512
#define GSM_ALO (512 + 16384)
#define GSM_BHI (512 + 32768)
#define GSM_BLO (512 + 49152)
#define GRAM_SMEM (512 + 65536)

__global__ void __launch_bounds__(256) gram_hmma_kernel() {
    extern __shared__ char smem[];
    float* xxs = (float*)(smem + GSM_XX);
    uint32_t sb = smem_u32(smem);
    int t = threadIdx.x, lane = t & 31, w = t >> 5;
    int b = blockIdx.z;
    int m0 = blockIdx.x * 128;
    int n0 = blockIdx.y * 128;

    if (t < 128) xxs[t] = g_xx[b * NN + n0 + t];

    {
        int row = t >> 1, half = t & 1;
        const uint4* gAh = (const uint4*)(g_xhi + ((size_t)(b * NN + m0 + row)) * 64) + half * 4;
        const uint4* gAl = (const uint4*)(g_xlo + ((size_t)(b * NN + m0 + row)) * 64) + half * 4;
        const uint4* gBh = (const uint4*)(g_xhi + ((size_t)(b * NN + n0 + row)) * 64) + half * 4;
        const uint4* gBl = (const uint4*)(g_xlo + ((size_t)(b * NN + n0 + row)) * 64) + half * 4;
        #pragma unroll
        for (int i = 0; i < 4; i++) {
            uint32_t off = SW128((uint32_t)(row * 128 + (half * 4 + i) * 16));
            *(uint4*)(smem + GSM_AHI + off) = gAh[i];
            *(uint4*)(smem + GSM_ALO + off) = gAl[i];
            *(uint4*)(smem + GSM_BHI + off) = gBh[i];
            *(uint4*)(smem + GSM_BLO + off) = gBl[i];
        }
    }
    __syncthreads();

    int wm = (w >> 1) * 32;
    int wn = (w & 1) * 64;

    float acc[2][8][4];
    #pragma unroll
    for (int mi = 0; mi < 2; mi++)
        #pragma unroll
        for (int ni = 0; ni < 8; ni++)
            #pragma unroll
            for (int j = 0; j < 4; j++) acc[mi][ni][j] = 0.f;

    int a_r = ((lane >> 3) & 1) * 8 + (lane & 7);
    int a_c = (lane >> 4) * 16;
    int b_r = (lane >> 4) * 8 + (lane & 7);
    int b_c = ((lane >> 3) & 1) * 16;

    #pragma unroll
    for (int pass = 0; pass < 3; pass++) {
        uint32_t abase = sb + (pass == 2 ? GSM_ALO : GSM_AHI);
        uint32_t bbase = sb + (pass == 1 ? GSM_BLO : GSM_BHI);
        #pragma unroll
        for (int kk = 0; kk < 4; kk++) {
            uint32_t a_frag[2][4];
            #pragma unroll
            for (int mi = 0; mi < 2; mi++) {
                int arow = wm + mi * 16 + a_r;
                uint32_t addr = abase + SW128((uint32_t)(arow * 128 + kk * 32 + a_c));
                asm volatile("ldmatrix.sync.aligned.m8n8.x4.shared.b16 {%0,%1,%2,%3}, [%4];"
                    : "=r"(a_frag[mi][0]), "=r"(a_frag[mi][1]),
                      "=r"(a_frag[mi][2]), "=r"(a_frag[mi][3])
                    : "r"(addr));
            }
            uint32_t b_frag[8][2];
            #pragma unroll
            for (int nb = 0; nb < 4; nb++) {
                int brow = wn + nb * 16 + b_r;
                uint32_t addr = bbase + SW128((uint32_t)(brow * 128 + kk * 32 + b_c));
                uint32_t r0, r1, r2, r3;
                asm volatile("ldmatrix.sync.aligned.m8n8.x4.shared.b16 {%0,%1,%2,%3}, [%4];"
                    : "=r"(r0), "=r"(r1), "=r"(r2), "=r"(r3) : "r"(addr));
                b_frag[nb * 2][0] = r0;     b_frag[nb * 2][1] = r1;
                b_frag[nb * 2 + 1][0] = r2; b_frag[nb * 2 + 1][1] = r3;
            }
            #pragma unroll
            for (int mi = 0; mi < 2; mi++)
                #pragma unroll
                for (int ni = 0; ni < 8; ni++)
                    asm volatile(
                        "mma.sync.aligned.m16n8k16.row.col.f32.bf16.bf16.f32 "
                        "{%0,%1,%2,%3}, {%4,%5,%6,%7}, {%8,%9}, {%0,%1,%2,%3};"
                        : "+f"(acc[mi][ni][0]), "+f"(acc[mi][ni][1]),
                          "+f"(acc[mi][ni][2]), "+f"(acc[mi][ni][3])
                        : "r"(a_frag[mi][0]), "r"(a_frag[mi][1]),
                          "r"(a_frag[mi][2]), "r"(a_frag[mi][3]),
                          "r"(b_frag[ni][0]), "r"(b_frag[ni][1]));
        }
    }

    int qrow = lane >> 2, qcol = (lane & 3) * 2;
    #pragma unroll
    for (int mi = 0; mi < 2; mi++) {
        int row0 = m0 + wm + mi * 16 + qrow;
        float* drow = g_gram + ((size_t)(b * NN + row0)) * NN + n0;
        #pragma unroll
        for (int ni = 0; ni < 8; ni++) {
            int col = wn + ni * 8 + qcol;
            float xx0 = xxs[col], xx1 = xxs[col + 1];
            *(float2*)(drow + col) =
                make_float2(2.f * acc[mi][ni][0] - xx0, 2.f * acc[mi][ni][1] - xx1);
            *(float2*)(drow + 8 * (size_t)NN + col) =
                make_float2(2.f * acc[mi][ni][2] - xx0, 2.f * acc[mi][ni][3] - xx1);
        }
    }
}

// ---------------- K3: top-32 per row (warp per row, per-lane top-4 buffer) ----
__device__ __forceinline__ int colof(int lane, int i) {
    return ((i >> 2) << 7) + (lane << 2) + (i & 3);
}

__global__ void topk_kernel() {
    int t = threadIdx.x;
    int lane = t & 31;
    int row = blockIdx.x * 8 + (t >> 5);      // b*N + n
    const float* srow = g_gram + (size_t)row * NN;

    float vals[64];
    #pragma unroll
    for (int j = 0; j < 16; j++) {
        float4 s4 = *(const float4*)&srow[j * 128 + lane * 4];
        vals[j * 4 + 0] = s4.x; vals[j * 4 + 1] = s4.y;
        vals[j * 4 + 2] = s4.z; vals[j * 4 + 3] = s4.w;
    }

    float b0 = -FLT_MAX, b1 = -FLT_MAX, b2 = -FLT_MAX, b3 = -FLT_MAX;
    int i0 = 0, i1 = 0, i2 = 0, i3 = 0;
    #pragma unroll
    for (int i = 0; i < 64; i++) {
        float v = vals[i];
        bool g0 = v > b0, g1 = v > b1, g2 = v > b2, g3 = v > b3;
        b3 = g2 ? b2 : (g3 ? v : b3);  i3 = g2 ? i2 : (g3 ? i : i3);
        b2 = g1 ? b1 : (g2 ? v : b2);  i2 = g1 ? i1 : (g2 ? i : i2);
        b1 = g0 ? b0 : (g1 ? v : b1);  i1 = g0 ? i0 : (g1 ? i : i1);
        b0 = g0 ? v  : b0;             i0 = g0 ? i  : i0;
    }

    unsigned long long dead = 0ull;
    int cnt = 4;
    int* orow = g_idx + row * 32;

    #pragma unroll 1
    for (int r = 0; r < 32; r++) {
        float v = b0;
        int gi = colof(lane, i0);
        #pragma unroll
        for (int off = 16; off; off >>= 1) {
            float ov = __shfl_xor_sync(0xffffffffu, v, off);
            int oi = __shfl_xor_sync(0xffffffffu, gi, off);
            if (ov > v || (ov == v && oi < gi)) { v = ov; gi = oi; }
        }
        if (lane == 0) orow[r] = gi;
        if (colof(lane, i0) == gi) {
            dead |= (1ull << i0);
            b0 = b1; i0 = i1; b1 = b2; i1 = i2; b2 = b3; i2 = i3; b3 = -FLT_MAX;
            if (--cnt == 0) {
                b0 = b1 = b2 = b3 = -FLT_MAX;
                #pragma unroll
                for (int i = 0; i < 64; i++) {
                    float v2 = ((dead >> i) & 1ull) ? -FLT_MAX : vals[i];
                    bool g0 = v2 > b0, g1 = v2 > b1, g2 = v2 > b2, g3 = v2 > b3;
                    b3 = g2 ? b2 : (g3 ? v2 : b3);  i3 = g2 ? i2 : (g3 ? i : i3);
                    b2 = g1 ? b1 : (g2 ? v2 : b2);  i2 = g1 ? i1 : (g2 ? i : i2);
                    b1 = g0 ? b0 : (g1 ? v2 : b1);  i1 = g0 ? i0 : (g1 ? i : i1);
                    b0 = g0 ? v2 : b0;              i0 = g0 ? i  : i0;
                }
                cnt = 4;
            }
        }
    }
}

// ---------------- K4: neighbor attention (warp per point, staged K gather) ---
// Block 256 = 8 warps. Dynamic smem: per-warp K staging 32 rows x 66 floats.
#define ATTN_STRIDE 66
#define ATTN_SMEM (8 * 32 * ATTN_STRIDE * 4)

__global__ void __launch_bounds__(256) attn_kernel() {
    extern __shared__ float stg_all[];
    __shared__ float sq[8][64], sk[8][64], sv[8][64];
    __shared__ float sa[8][32][8];
    __shared__ int smi[8][32];
    int t = threadIdx.x, lane = t & 31, wl = t >> 5;
    int pt = blockIdx.x * 8 + wl;
    int b = pt >> 11;
    size_t base = (size_t)pt * 64;
    float* st = stg_all + wl * 32 * ATTN_STRIDE;

    sq[wl][lane] = g_qT[base + lane];  sq[wl][lane + 32] = g_qT[base + lane + 32];
    sk[wl][lane] = g_kT[base + lane];  sk[wl][lane + 32] = g_kT[base + lane + 32];
    sv[wl][lane] = g_vT[base + lane];  sv[wl][lane + 32] = g_vT[base + lane + 32];
    int m = g_idx[pt * 32 + lane];
    smi[wl][lane] = m;
    __syncwarp();

    // stage 32 neighbor K rows cooperatively (coalesced 256B rows)
    #pragma unroll 8
    for (int k = 0; k < 32; k++) {
        int mm = smi[wl][k];
        const float2* kr = (const float2*)(g_kT + ((size_t)(b * NN + mm)) * 64);
        *(float2*)&st[k * ATTN_STRIDE + lane * 2] = kr[lane];
    }
    __syncwarp();

    // energies: lane owns neighbor `lane`, reads its staged row (conflict-free)
    float e[8] = {0, 0, 0, 0, 0, 0, 0, 0};
    #pragma unroll
    for (int cc = 0; cc < 32; cc++) {
        float2 kv = *(const float2*)&st[lane * ATTN_STRIDE + cc * 2];
        int c = cc * 2, h = cc >> 2;
        e[h] += sq[wl][c] * (kv.x - sk[wl][c])
              + sq[wl][c + 1] * (kv.y - sk[wl][c + 1]);
    }

    const float scale = 0.3535533905932738f;
    #pragma unroll
    for (int h = 0; h < 8; h++) {
        float es = e[h] * scale;
        float mx = es;
        #pragma unroll
        for (int off = 16; off; off >>= 1)
            mx = fmaxf(mx, __shfl_xor_sync(0xffffffffu, mx, off));
        float p = __expf(es - mx);
        float s = p;
        #pragma unroll
        for (int off = 16; off; off >>= 1)
            s += __shfl_xor_sync(0xffffffffu, s, off);
        sa[wl][lane][h] = p / s;
    }
    __syncwarp();

    // weighted V sum (already coalesced: lane = channel)
    int c1 = lane, c2 = lane + 32;
    int h1 = lane >> 3, h2 = h1 + 4;
    float svc1 = sv[wl][c1], svc2 = sv[wl][c2];
    float acc1 = 0.f, acc2 = 0.f;
    #pragma unroll
    for (int k = 0; k < 32; k++) {
        int mm = smi[wl][k];
        const float* vrow = g_vT + ((size_t)(b * NN + mm)) * 64;
        acc1 += sa[wl][k][h1] * (vrow[c1] - svc1);
        acc2 += sa[wl][k][h2] * (vrow[c2] - svc2);
    }
    g_attnT[base + c1] = acc1;
    g_attnT[base + c2] = acc2;
}

// ---------------- K5: y1 = x + attn; partial BN1 stats ----------------
__global__ void bn1_kernel(const float* __restrict__ x) {
    int n = blockIdx.x * 256 + threadIdx.x;
    int c = blockIdx.y, b = blockIdx.z;
    float v = x[((size_t)(b * 64 + c)) * NN + n]
            + g_attnT[((size_t)(b * NN + n)) * 64 + c];
    g_y1T[((size_t)(b * NN + n)) * 64 + c] = v;

    float s = v, ss = v * v;
    #pragma unroll
    for (int off = 16; off; off >>= 1) {
        s += __shfl_xor_sync(0xffffffffu, s, off);
        ss += __shfl_xor_sync(0xffffffffu, ss, off);
    }
    __shared__ float rs[8], rss[8];
    if ((threadIdx.x & 31) == 0) { rs[threadIdx.x >> 5] = s; rss[threadIdx.x >> 5] = ss; }
    __syncthreads();
    if (threadIdx.x == 0) {
        float S = 0, SS = 0;
        #pragma unroll
        for (int w = 0; w < 8; w++) { S += rs[w]; SS += rss[w]; }
        int bi = blockIdx.z * 8 + blockIdx.x;
        g_p1s[c * 64 + bi] = S;
        g_p1ss[c * 64 + bi] = SS;
    }
}

__global__ void finalize1_kernel(const float* __restrict__ gamma,
                                 const float* __restrict__ beta) {
    int c = threadIdx.x;
    if (c >= 64) return;
    float S = 0, SS = 0;
    for (int i = 0; i < 64; i++) { S += g_p1s[c * 64 + i]; SS += g_p1ss[c * 64 + i]; }
    float mean = S * (1.f / 16384.f);
    float var = SS * (1.f / 16384.f) - mean * mean;
    float r = rsqrtf(var + 1e-5f);
    float sc = gamma[c] * r;
    g_sc1[c] = sc;
    g_sh1[c] = beta[c] - mean * sc;
}

// ---------------- K6: fused FFN (h = leaky(W1@x1); y2 = x1 + W2@h) ----------
// grid (64, 8), block 128. Dynamic smem layout (floats):
#define FSM_W1 0                        // [64][128]: W1s[c*128+o]
#define FSM_W2 (64 * 128)               // [128][65]: W2s[j*65+c]
#define FSM_XV (FSM_W2 + 128 * 65)      // [64]
#define FSM_HV (FSM_XV + 64)            // [128]
#define FSM_RED (FSM_HV + 128)          // [128]
#define FSM_X1 (FSM_RED + 128)          // [64]
#define FSM_SC (FSM_X1 + 64)            // [64]
#define FSM_SH (FSM_SC + 64)            // [64]
#define FFN_SMEM ((FSM_SH + 64) * 4)

__global__ void __launch_bounds__(128) ffn_fused_kernel(const float* __restrict__ W1,
                                                        const float* __restrict__ W2) {
    extern __shared__ float fsm[];
    float* W1s = fsm + FSM_W1;
    float* W2s = fsm + FSM_W2;
    float* xv  = fsm + FSM_XV;
    float* hv  = fsm + FSM_HV;
    float* red = fsm + FSM_RED;
    float* x1s = fsm + FSM_X1;
    float* sc  = fsm + FSM_SC;
    float* sh  = fsm + FSM_SH;
    int t = threadIdx.x;

    #pragma unroll 8
    for (int i = 0; i < 64; i++) {
        int e = t + i * 128;                 // 0..8191
        W1s[(e & 63) * 128 + (e >> 6)] = W1[e];
        W2s[(e & 127) * 65 + (e >> 7)] = W2[e];
    }
    if (t < 64) { sc[t] = g_sc1[t]; sh[t] = g_sh1[t]; }
    int b = blockIdx.y;
    int n0 = blockIdx.x * 32;
    __syncthreads();

    int c = t & 63, jh = t >> 6;             // phase-2 split
    float lsum = 0.f, lss = 0.f;

    for (int p = 0; p < 32; p++) {
        size_t pt = (size_t)(b * NN + n0 + p);
        if (t < 64) {
            float x1 = g_y1T[pt * 64 + t] * sc[t] + sh[t];
            xv[t] = x1; x1s[t] = x1;
        }
        __syncthreads();
        // phase 1: h[t] = leaky(W1[t,:] . x1)
        float a0 = 0.f, a1 = 0.f;
        #pragma unroll
        for (int cc = 0; cc < 32; cc++) {
            a0 += W1s[(2 * cc) * 128 + t] * xv[2 * cc];
            a1 += W1s[(2 * cc + 1) * 128 + t] * xv[2 * cc + 1];
        }
        float h = a0 + a1;
        hv[t] = h > 0.f ? h : 0.2f * h;
        __syncthreads();
        // phase 2: y2[c] = x1[c] + W2[c,:] . h, split across two j-halves
        float p0 = 0.f, p1 = 0.f;
        #pragma unroll
        for (int jj = 0; jj < 32; jj++) {
            int j = jh * 64 + 2 * jj;
            p0 += W2s[j * 65 + c] * hv[j];
            p1 += W2s[(j + 1) * 65 + c] * hv[j + 1];
        }
        red[t] = p0 + p1;
        __syncthreads();
        if (t < 64) {
            float y2 = x1s[t] + red[t] + red[t + 64];
            g_y2T[pt * 64 + t] = y2;
            lsum += y2; lss += y2 * y2;
        }
        __syncthreads();
    }
    if (t < 64) {
        int bi = b * 64 + blockIdx.x;
        g_p2s[t * 512 + bi] = lsum;
        g_p2ss[t * 512 + bi] = lss;
    }
}

__global__ void finalize2_kernel(const float* __restrict__ gamma,
                                 const float* __restrict__ beta) {
    int c = threadIdx.x;
    if (c >= 64) return;
    float S = 0, SS = 0;
    for (int i = 0; i < 512; i++) { S += g_p2s[c * 512 + i]; SS += g_p2ss[c * 512 + i]; }
    float mean = S * (1.f / 16384.f);
    float var = SS * (1.f / 16384.f) - mean * mean;
    float r = rsqrtf(var + 1e-5f);
    float sc = gamma[c] * r;
    g_sc2[c] = sc;
    g_sh2[c] = beta[c] - mean * sc;
}

// ---------------- K7: apply BN2 -> output (B,C,N) ----------------
__global__ void apply_bn2_kernel(float* __restrict__ out) {
    int i = blockIdx.x * 256 + threadIdx.x;
    int n = i & 2047;
    int c = (i >> 11) & 63;
    int b = i >> 17;
    float v = g_y2T[((size_t)(b * NN + n)) * 64 + c];
    out[i] = v * g_sc2[c] + g_sh2[c];
}

// ---------------- launch ----------------
extern "C" void kernel_launch(void* const* d_in, const int* in_sizes, int n_in,
                              void* d_out, int out_size) {
    const float* x  = (const float*)d_in[0];
    const float* Wq = (const float*)d_in[1];
    const float* Wk = (const float*)d_in[2];
    const float* Wv = (const float*)d_in[3];
    const float* W1 = (const float*)d_in[4];
    const float* W2 = (const float*)d_in[5];
    const float* g1 = (const float*)d_in[6];
    const float* b1 = (const float*)d_in[7];
    const float* g2 = (const float*)d_in[8];
    const float* b2 = (const float*)d_in[9];
    float* out = (float*)d_out;

    cudaFuncSetAttribute(gram_hmma_kernel,
                         cudaFuncAttributeMaxDynamicSharedMemorySize, GRAM_SMEM);
    cudaFuncSetAttribute(attn_kernel,
                         cudaFuncAttributeMaxDynamicSharedMemorySize, ATTN_SMEM);
    cudaFuncSetAttribute(ffn_fused_kernel,
                         cudaFuncAttributeMaxDynamicSharedMemorySize, FFN_SMEM);

    proj_kernel<<<dim3(64, 8), 256>>>(x, Wq, Wk, Wv);
    gram_hmma_kernel<<<dim3(16, 16, 8), 256, GRAM_SMEM>>>();
    topk_kernel<<<2048, 256>>>();
    attn_kernel<<<2048, 256, ATTN_SMEM>>>();
    bn1_kernel<<<dim3(8, 64, 8), 256>>>(x);
    finalize1_kernel<<<1, 64>>>(g1, b1);
    ffn_fused_kernel<<<dim3(64, 8), 128, FFN_SMEM>>>(W1, W2);
    finalize2_kernel<<<1, 64>>>(g2, b2);
    apply_bn2_kernel<<<4096, 256>>>(out);
}

// round 15
// speedup vs baseline: 1.1097x; 1.1097x over previous
#include <cuda_runtime.h>
#include <cuda_bf16.h>
#include <stdint.h>
#include <math.h>
#include <float.h>

#define BB 8
#define CC 64
#define NN 2048
#define KK 32

// ---------------- scratch (device globals) ----------------
__device__ float g_gram[(size_t)BB * NN * NN];      // scores: 2*inner - xx[col]
__device__ __nv_bfloat16 g_xhi[BB * NN * CC];       // (B,N,64) bf16 hi, row-major
__device__ __nv_bfloat16 g_xlo[BB * NN * CC];       // bf16 lo residual
__device__ float g_qT[BB * NN * CC];
__device__ float g_kT[BB * NN * CC];
__device__ float g_vT[BB * NN * CC];
__device__ float g_xx[BB * NN];
__device__ int   g_idx[BB * NN * KK];
__device__ float g_attnT[BB * NN * CC];
__device__ float g_y1T[BB * NN * CC];
__device__ float g_hT[BB * NN * 128];
__device__ float g_y2T[BB * NN * CC];
__device__ float g_p1s[64 * 256], g_p1ss[64 * 256];
__device__ float g_p2s[64 * 512], g_p2ss[64 * 512];
__device__ float g_sc1[64], g_sh1[64], g_sc2[64], g_sh2[64];

// ---------------- helpers ----------------
__device__ __forceinline__ uint32_t smem_u32(const void* p) {
    uint32_t a;
    asm("{ .reg .u64 t; cvta.to.shared.u64 t, %1; cvt.u32.u64 %0, t; }" : "=r"(a) : "l"(p));
    return a;
}
#define SW128(off) ((off) ^ (((off) >> 3) & 0x70))

// ---------------- K1: projections + norms + bf16 hi/lo split ----------------
__global__ void proj_kernel(const float* __restrict__ x,
                            const float* __restrict__ Wq,
                            const float* __restrict__ Wk,
                            const float* __restrict__ Wv) {
    __shared__ float xs[64][33];
    __shared__ float os[32][65];
    int b = blockIdx.y;
    int n0 = blockIdx.x * 32;
    int t = threadIdx.x;
    const float* xb = x + (size_t)b * CC * NN;

    #pragma unroll
    for (int i = 0; i < 8; i++) {
        int e = t + i * 256;
        int c = e >> 5, j = e & 31;
        xs[c][j] = xb[c * NN + n0 + j];
    }
    __syncthreads();

    if (t < 32) {
        float s = 0.f;
        #pragma unroll
        for (int c = 0; c < 64; c++) { float v = xs[c][t]; s += v * v; }
        g_xx[b * NN + n0 + t] = s;
    }

    // bf16 hi/lo transposed write: (B,N,64)
    #pragma unroll
    for (int i = 0; i < 4; i++) {
        int e = t + i * 256;         // 0..1023
        int p = e >> 5;              // point 0..31
        int cp = e & 31;             // channel pair 0..31
        float v0 = xs[cp * 2][p], v1 = xs[cp * 2 + 1][p];
        __nv_bfloat16 h0 = __float2bfloat16(v0);
        __nv_bfloat16 h1 = __float2bfloat16(v1);
        __nv_bfloat16 l0 = __float2bfloat16(v0 - __bfloat162float(h0));
        __nv_bfloat16 l1 = __float2bfloat16(v1 - __bfloat162float(h1));
        size_t off = ((size_t)(b * NN + n0 + p)) * 64 + cp * 2;
        __nv_bfloat162 hh; hh.x = h0; hh.y = h1;
        __nv_bfloat162 ll; ll.x = l0; ll.y = l1;
        *(__nv_bfloat162*)(g_xhi + off) = hh;
        *(__nv_bfloat162*)(g_xlo + off) = ll;
    }

    int lane = t & 31;
    int w = t >> 5;
    const float* Ws[3] = {Wq, Wk, Wv};
    float* Os[3] = {g_qT, g_kT, g_vT};

    #pragma unroll
    for (int mtx = 0; mtx < 3; mtx++) {
        const float* W = Ws[mtx];
        #pragma unroll
        for (int p = 0; p < 8; p++) {
            int o = p * 8 + w;
            float s = 0.f;
            #pragma unroll
            for (int c = 0; c < 64; c++) s += W[o * 64 + c] * xs[c][lane];
            os[lane][o] = s;
        }
        __syncthreads();
        float* Ob = Os[mtx] + ((size_t)(b * NN + n0)) * 64;
        #pragma unroll
        for (int q = 0; q < 8; q++) {
            int e = t + q * 256;
            int pt = e >> 6, o = e & 63;
            Ob[pt * 64 + o] = os[pt][o];
        }
        __syncthreads();
    }
}

// ---------------- K2: Gram via mma.sync bf16 split (HMMA) ----------------
#define GSM_XX 0
#define GSM_AHI 512
#define GSM_ALO (512 + 16384)
#define GSM_BHI (512 + 32768)
#define GSM_BLO (512 + 49152)
#define GRAM_SMEM (512 + 65536)

__global__ void __launch_bounds__(256) gram_hmma_kernel() {
    extern __shared__ char smem[];
    float* xxs = (float*)(smem + GSM_XX);
    uint32_t sb = smem_u32(smem);
    int t = threadIdx.x, lane = t & 31, w = t >> 5;
    int b = blockIdx.z;
    int m0 = blockIdx.x * 128;
    int n0 = blockIdx.y * 128;

    if (t < 128) xxs[t] = g_xx[b * NN + n0 + t];

    {
        int row = t >> 1, half = t & 1;
        const uint4* gAh = (const uint4*)(g_xhi + ((size_t)(b * NN + m0 + row)) * 64) + half * 4;
        const uint4* gAl = (const uint4*)(g_xlo + ((size_t)(b * NN + m0 + row)) * 64) + half * 4;
        const uint4* gBh = (const uint4*)(g_xhi + ((size_t)(b * NN + n0 + row)) * 64) + half * 4;
        const uint4* gBl = (const uint4*)(g_xlo + ((size_t)(b * NN + n0 + row)) * 64) + half * 4;
        #pragma unroll
        for (int i = 0; i < 4; i++) {
            uint32_t off = SW128((uint32_t)(row * 128 + (half * 4 + i) * 16));
            *(uint4*)(smem + GSM_AHI + off) = gAh[i];
            *(uint4*)(smem + GSM_ALO + off) = gAl[i];
            *(uint4*)(smem + GSM_BHI + off) = gBh[i];
            *(uint4*)(smem + GSM_BLO + off) = gBl[i];
        }
    }
    __syncthreads();

    int wm = (w >> 1) * 32;
    int wn = (w & 1) * 64;

    float acc[2][8][4];
    #pragma unroll
    for (int mi = 0; mi < 2; mi++)
        #pragma unroll
        for (int ni = 0; ni < 8; ni++)
            #pragma unroll
            for (int j = 0; j < 4; j++) acc[mi][ni][j] = 0.f;

    int a_r = ((lane >> 3) & 1) * 8 + (lane & 7);
    int a_c = (lane >> 4) * 16;
    int b_r = (lane >> 4) * 8 + (lane & 7);
    int b_c = ((lane >> 3) & 1) * 16;

    #pragma unroll
    for (int pass = 0; pass < 3; pass++) {
        uint32_t abase = sb + (pass == 2 ? GSM_ALO : GSM_AHI);
        uint32_t bbase = sb + (pass == 1 ? GSM_BLO : GSM_BHI);
        #pragma unroll
        for (int kk = 0; kk < 4; kk++) {
            uint32_t a_frag[2][4];
            #pragma unroll
            for (int mi = 0; mi < 2; mi++) {
                int arow = wm + mi * 16 + a_r;
                uint32_t addr = abase + SW128((uint32_t)(arow * 128 + kk * 32 + a_c));
                asm volatile("ldmatrix.sync.aligned.m8n8.x4.shared.b16 {%0,%1,%2,%3}, [%4];"
                    : "=r"(a_frag[mi][0]), "=r"(a_frag[mi][1]),
                      "=r"(a_frag[mi][2]), "=r"(a_frag[mi][3])
                    : "r"(addr));
            }
            uint32_t b_frag[8][2];
            #pragma unroll
            for (int nb = 0; nb < 4; nb++) {
                int brow = wn + nb * 16 + b_r;
                uint32_t addr = bbase + SW128((uint32_t)(brow * 128 + kk * 32 + b_c));
                uint32_t r0, r1, r2, r3;
                asm volatile("ldmatrix.sync.aligned.m8n8.x4.shared.b16 {%0,%1,%2,%3}, [%4];"
                    : "=r"(r0), "=r"(r1), "=r"(r2), "=r"(r3) : "r"(addr));
                b_frag[nb * 2][0] = r0;     b_frag[nb * 2][1] = r1;
                b_frag[nb * 2 + 1][0] = r2; b_frag[nb * 2 + 1][1] = r3;
            }
            #pragma unroll
            for (int mi = 0; mi < 2; mi++)
                #pragma unroll
                for (int ni = 0; ni < 8; ni++)
                    asm volatile(
                        "mma.sync.aligned.m16n8k16.row.col.f32.bf16.bf16.f32 "
                        "{%0,%1,%2,%3}, {%4,%5,%6,%7}, {%8,%9}, {%0,%1,%2,%3};"
                        : "+f"(acc[mi][ni][0]), "+f"(acc[mi][ni][1]),
                          "+f"(acc[mi][ni][2]), "+f"(acc[mi][ni][3])
                        : "r"(a_frag[mi][0]), "r"(a_frag[mi][1]),
                          "r"(a_frag[mi][2]), "r"(a_frag[mi][3]),
                          "r"(b_frag[ni][0]), "r"(b_frag[ni][1]));
        }
    }

    int qrow = lane >> 2, qcol = (lane & 3) * 2;
    #pragma unroll
    for (int mi = 0; mi < 2; mi++) {
        int row0 = m0 + wm + mi * 16 + qrow;
        float* drow = g_gram + ((size_t)(b * NN + row0)) * NN + n0;
        #pragma unroll
        for (int ni = 0; ni < 8; ni++) {
            int col = wn + ni * 8 + qcol;
            float xx0 = xxs[col], xx1 = xxs[col + 1];
            *(float2*)(drow + col) =
                make_float2(2.f * acc[mi][ni][0] - xx0, 2.f * acc[mi][ni][1] - xx1);
            *(float2*)(drow + 8 * (size_t)NN + col) =
                make_float2(2.f * acc[mi][ni][2] - xx0, 2.f * acc[mi][ni][3] - xx1);
        }
    }
}

// ---------------- K3: top-32 per row (warp per row, per-lane top-4 buffer) ----
__device__ __forceinline__ int colof(int lane, int i) {
    return ((i >> 2) << 7) + (lane << 2) + (i & 3);
}

__global__ void topk_kernel() {
    int t = threadIdx.x;
    int lane = t & 31;
    int row = blockIdx.x * 8 + (t >> 5);      // b*N + n
    const float* srow = g_gram + (size_t)row * NN;

    float vals[64];
    #pragma unroll
    for (int j = 0; j < 16; j++) {
        float4 s4 = *(const float4*)&srow[j * 128 + lane * 4];
        vals[j * 4 + 0] = s4.x; vals[j * 4 + 1] = s4.y;
        vals[j * 4 + 2] = s4.z; vals[j * 4 + 3] = s4.w;
    }

    float b0 = -FLT_MAX, b1 = -FLT_MAX, b2 = -FLT_MAX, b3 = -FLT_MAX;
    int i0 = 0, i1 = 0, i2 = 0, i3 = 0;
    #pragma unroll
    for (int i = 0; i < 64; i++) {
        float v = vals[i];
        bool g0 = v > b0, g1 = v > b1, g2 = v > b2, g3 = v > b3;
        b3 = g2 ? b2 : (g3 ? v : b3);  i3 = g2 ? i2 : (g3 ? i : i3);
        b2 = g1 ? b1 : (g2 ? v : b2);  i2 = g1 ? i1 : (g2 ? i : i2);
        b1 = g0 ? b0 : (g1 ? v : b1);  i1 = g0 ? i0 : (g1 ? i : i1);
        b0 = g0 ? v  : b0;             i0 = g0 ? i  : i0;
    }

    unsigned long long dead = 0ull;
    int cnt = 4;
    int* orow = g_idx + row * 32;

    #pragma unroll 1
    for (int r = 0; r < 32; r++) {
        float v = b0;
        int gi = colof(lane, i0);
        #pragma unroll
        for (int off = 16; off; off >>= 1) {
            float ov = __shfl_xor_sync(0xffffffffu, v, off);
            int oi = __shfl_xor_sync(0xffffffffu, gi, off);
            if (ov > v || (ov == v && oi < gi)) { v = ov; gi = oi; }
        }
        if (lane == 0) orow[r] = gi;
        if (colof(lane, i0) == gi) {
            dead |= (1ull << i0);
            b0 = b1; i0 = i1; b1 = b2; i1 = i2; b2 = b3; i2 = i3; b3 = -FLT_MAX;
            if (--cnt == 0) {
                b0 = b1 = b2 = b3 = -FLT_MAX;
                #pragma unroll
                for (int i = 0; i < 64; i++) {
                    float v2 = ((dead >> i) & 1ull) ? -FLT_MAX : vals[i];
                    bool g0 = v2 > b0, g1 = v2 > b1, g2 = v2 > b2, g3 = v2 > b3;
                    b3 = g2 ? b2 : (g3 ? v2 : b3);  i3 = g2 ? i2 : (g3 ? i : i3);
                    b2 = g1 ? b1 : (g2 ? v2 : b2);  i2 = g1 ? i1 : (g2 ? i : i2);
                    b1 = g0 ? b0 : (g1 ? v2 : b1);  i1 = g0 ? i0 : (g1 ? i : i1);
                    b0 = g0 ? v2 : b0;              i0 = g0 ? i  : i0;
                }
                cnt = 4;
            }
        }
    }
}

// ---------------- K4: attention (warp/point, cooperative energy reduction) --
// No dynamic smem -> full occupancy. Energy: all 32 lanes load each neighbor
// row cooperatively (coalesced float2), partial dot, 4-lane xor-reduce to heads.
__global__ void __launch_bounds__(256) attn_kernel() {
    __shared__ float sq[8][64], sk[8][64], sv[8][64];
    __shared__ float sa[8][32][9];          // stride 9: conflict-free reads
    __shared__ int smi[8][32];
    int t = threadIdx.x, lane = t & 31, wl = t >> 5;
    int pt = blockIdx.x * 8 + wl;
    int b = pt >> 11;
    size_t base = (size_t)pt * 64;

    sq[wl][lane] = g_qT[base + lane];  sq[wl][lane + 32] = g_qT[base + lane + 32];
    sk[wl][lane] = g_kT[base + lane];  sk[wl][lane + 32] = g_kT[base + lane + 32];
    sv[wl][lane] = g_vT[base + lane];  sv[wl][lane + 32] = g_vT[base + lane + 32];
    smi[wl][lane] = g_idx[pt * 32 + lane];
    __syncwarp();

    // lane owns channel pair (2*lane, 2*lane+1); head of this pair = lane>>2
    int c0 = lane * 2;
    int myh = lane >> 2;
    float q0 = sq[wl][c0], q1 = sq[wl][c0 + 1];
    float k0 = sk[wl][c0], k1 = sk[wl][c0 + 1];
    bool writer = (lane & 3) == 0;

    #pragma unroll 4
    for (int k = 0; k < 32; k++) {
        int mm = smi[wl][k];
        float2 kv = ((const float2*)(g_kT + ((size_t)(b * NN + mm)) * 64))[lane];
        float p = q0 * (kv.x - k0) + q1 * (kv.y - k1);
        p += __shfl_xor_sync(0xffffffffu, p, 1);
        p += __shfl_xor_sync(0xffffffffu, p, 2);
        if (writer) sa[wl][k][myh] = p;     // 8 writers, consecutive banks
    }
    __syncwarp();

    // softmax: lane = neighbor index, 8 heads in registers
    const float scale = 0.3535533905932738f;
    float e[8];
    #pragma unroll
    for (int h = 0; h < 8; h++) e[h] = sa[wl][lane][h] * scale;
    #pragma unroll
    for (int h = 0; h < 8; h++) {
        float mx = e[h];
        #pragma unroll
        for (int off = 16; off; off >>= 1)
            mx = fmaxf(mx, __shfl_xor_sync(0xffffffffu, mx, off));
        float p = __expf(e[h] - mx);
        float s = p;
        #pragma unroll
        for (int off = 16; off; off >>= 1)
            s += __shfl_xor_sync(0xffffffffu, s, off);
        sa[wl][lane][h] = p / s;
    }
    __syncwarp();

    // weighted V sum (coalesced: lane = channel)
    int c1 = lane, c2 = lane + 32;
    int h1 = lane >> 3, h2 = h1 + 4;
    float svc1 = sv[wl][c1], svc2 = sv[wl][c2];
    float acc1 = 0.f, acc2 = 0.f;
    #pragma unroll 8
    for (int k = 0; k < 32; k++) {
        int mm = smi[wl][k];
        const float* vrow = g_vT + ((size_t)(b * NN + mm)) * 64;
        acc1 += sa[wl][k][h1] * (vrow[c1] - svc1);
        acc2 += sa[wl][k][h2] * (vrow[c2] - svc2);
    }
    g_attnT[base + c1] = acc1;
    g_attnT[base + c2] = acc2;
}

// ---------------- K5: y1 = x + attn (tile transpose); partial BN1 stats -----
// grid (32, 8): 64-point tile per block, block 256.
__global__ void __launch_bounds__(256) bn1_kernel(const float* __restrict__ x) {
    __shared__ float xt[64][65];
    __shared__ float red[4][64], redss[4][64];
    int t = threadIdx.x;
    int b = blockIdx.y;
    int n0 = blockIdx.x * 64;
    const float* xb = x + (size_t)b * CC * NN;

    // load x tile coalesced: (c, n)
    #pragma unroll
    for (int i = 0; i < 16; i++) {
        int e = t + i * 256;
        int c = e >> 6, n = e & 63;
        xt[c][n] = xb[c * NN + n0 + n];
    }
    __syncthreads();

    // add attnT (coalesced rows), write y1T (coalesced), accumulate stats
    int ch = t & 63, pg = t >> 6;             // thread's fixed channel, point group
    float lsum = 0.f, lss = 0.f;
    #pragma unroll
    for (int i = 0; i < 16; i++) {
        int p = pg + i * 4;
        size_t row = ((size_t)(b * NN + n0 + p)) * 64;
        float v = xt[ch][p] + g_attnT[row + ch];
        g_y1T[row + ch] = v;
        lsum += v; lss += v * v;
    }
    red[pg][ch] = lsum; redss[pg][ch] = lss;
    __syncthreads();
    if (t < 64) {
        float S = red[0][t] + red[1][t] + red[2][t] + red[3][t];
        float SS = redss[0][t] + redss[1][t] + redss[2][t] + redss[3][t];
        int bi = b * 32 + blockIdx.x;         // 0..255 per channel
        g_p1s[t * 256 + bi] = S;
        g_p1ss[t * 256 + bi] = SS;
    }
}

__global__ void finalize1_kernel(const float* __restrict__ gamma,
                                 const float* __restrict__ beta) {
    int c = threadIdx.x;
    if (c >= 64) return;
    float S = 0, SS = 0;
    for (int i = 0; i < 256; i++) { S += g_p1s[c * 256 + i]; SS += g_p1ss[c * 256 + i]; }
    float mean = S * (1.f / 16384.f);
    float var = SS * (1.f / 16384.f) - mean * mean;
    float r = rsqrtf(var + 1e-5f);
    float sc = gamma[c] * r;
    g_sc1[c] = sc;
    g_sh1[c] = beta[c] - mean * sc;
}

// ---------------- K6a: h = leaky(W1 @ BN1(y1)) ----------------
__global__ void ffn1_kernel(const float* __restrict__ W1) {
    __shared__ float W1s[64][129];
    __shared__ float xv[64];
    __shared__ float sc[64], sh[64];
    int t = threadIdx.x;
    #pragma unroll 8
    for (int i = 0; i < 64; i++) {
        int e = t + i * 128;
        int o = e >> 6, c = e & 63;
        W1s[c][o] = W1[e];
    }
    if (t < 64) { sc[t] = g_sc1[t]; sh[t] = g_sh1[t]; }
    int b = blockIdx.y;
    int n0 = blockIdx.x * 32;
    __syncthreads();

    for (int p = 0; p < 32; p++) {
        size_t pt = (size_t)(b * NN + n0 + p);
        if (t < 64) xv[t] = g_y1T[pt * 64 + t] * sc[t] + sh[t];
        __syncthreads();
        float acc = 0.f;
        #pragma unroll
        for (int c = 0; c < 64; c++) acc += W1s[c][t] * xv[c];
        g_hT[pt * 128 + t] = acc > 0.f ? acc : 0.2f * acc;
        __syncthreads();
    }
}

// ---------------- K6b: y2 = x1 + W2 @ h; partial BN2 stats ----------------
__global__ void ffn2_kernel(const float* __restrict__ W2) {
    __shared__ float W2s[128][65];
    __shared__ float hv[128];
    __shared__ float sc[64], sh[64];
    int t = threadIdx.x;
    #pragma unroll 8
    for (int i = 0; i < 128; i++) {
        int e = t + i * 64;
        int o = e >> 7, j = e & 127;
        W2s[j][o] = W2[e];
    }
    sc[t] = g_sc1[t]; sh[t] = g_sh1[t];
    int b = blockIdx.y;
    int n0 = blockIdx.x * 32;
    __syncthreads();

    float lsum = 0.f, lss = 0.f;
    for (int p = 0; p < 32; p++) {
        size_t pt = (size_t)(b * NN + n0 + p);
        hv[t] = g_hT[pt * 128 + t];
        hv[t + 64] = g_hT[pt * 128 + t + 64];
        __syncthreads();
        float acc = 0.f;
        #pragma unroll
        for (int j = 0; j < 128; j++) acc += W2s[j][t] * hv[j];
        float x1 = g_y1T[pt * 64 + t] * sc[t] + sh[t];
        float y2 = x1 + acc;
        g_y2T[pt * 64 + t] = y2;
        lsum += y2; lss += y2 * y2;
        __syncthreads();
    }
    int bi = b * 64 + blockIdx.x;
    g_p2s[t * 512 + bi] = lsum;
    g_p2ss[t * 512 + bi] = lss;
}

__global__ void finalize2_kernel(const float* __restrict__ gamma,
                                 const float* __restrict__ beta) {
    int c = threadIdx.x;
    if (c >= 64) return;
    float S = 0, SS = 0;
    for (int i = 0; i < 512; i++) { S += g_p2s[c * 512 + i]; SS += g_p2ss[c * 512 + i]; }
    float mean = S * (1.f / 16384.f);
    float var = SS * (1.f / 16384.f) - mean * mean;
    float r = rsqrtf(var + 1e-5f);
    float sc = gamma[c] * r;
    g_sc2[c] = sc;
    g_sh2[c] = beta[c] - mean * sc;
}

// ---------------- K7: apply BN2 -> output (B,C,N), tile transpose ----------
// grid (32, 8), block 256.
__global__ void __launch_bounds__(256) apply_bn2_kernel(float* __restrict__ out) {
    __shared__ float yt[64][65];
    int t = threadIdx.x;
    int b = blockIdx.y;
    int n0 = blockIdx.x * 64;

    // read y2T coalesced (point-major rows)
    #pragma unroll
    for (int i = 0; i < 16; i++) {
        int e = t + i * 256;
        int p = e >> 6, ch = e & 63;
        yt[ch][p] = g_y2T[((size_t)(b * NN + n0 + p)) * 64 + ch];
    }
    __syncthreads();

    // write out coalesced (channel-major rows)
    float* ob = out + (size_t)b * CC * NN;
    #pragma unroll
    for (int i = 0; i < 16; i++) {
        int e = t + i * 256;
        int c = e >> 6, n = e & 63;
        ob[c * NN + n0 + n] = yt[c][n] * g_sc2[c] + g_sh2[c];
    }
}

// ---------------- launch ----------------
extern "C" void kernel_launch(void* const* d_in, const int* in_sizes, int n_in,
                              void* d_out, int out_size) {
    const float* x  = (const float*)d_in[0];
    const float* Wq = (const float*)d_in[1];
    const float* Wk = (const float*)d_in[2];
    const float* Wv = (const float*)d_in[3];
    const float* W1 = (const float*)d_in[4];
    const float* W2 = (const float*)d_in[5];
    const float* g1 = (const float*)d_in[6];
    const float* b1 = (const float*)d_in[7];
    const float* g2 = (const float*)d_in[8];
    const float* b2 = (const float*)d_in[9];
    float* out = (float*)d_out;

    cudaFuncSetAttribute(gram_hmma_kernel,
                         cudaFuncAttributeMaxDynamicSharedMemorySize, GRAM_SMEM);

    proj_kernel<<<dim3(64, 8), 256>>>(x, Wq, Wk, Wv);
    gram_hmma_kernel<<<dim3(16, 16, 8), 256, GRAM_SMEM>>>();
    topk_kernel<<<2048, 256>>>();
    attn_kernel<<<2048, 256>>>();
    bn1_kernel<<<dim3(32, 8), 256>>>(x);
    finalize1_kernel<<<1, 64>>>(g1, b1);
    ffn1_kernel<<<dim3(64, 8), 128>>>(W1);
    ffn2_kernel<<<dim3(64, 8), 64>>>(W2);
    finalize2_kernel<<<1, 64>>>(g2, b2);
    apply_bn2_kernel<<<dim3(32, 8), 256>>>(out);
}

// round 17
// speedup vs baseline: 1.2927x; 1.1648x over previous
#include <cuda_runtime.h>
#include <cuda_bf16.h>
#include <stdint.h>
#include <math.h>
#include <float.h>

#define BB 8
#define CC 64
#define NN 2048
#define KK 32

// ---------------- scratch (device globals) ----------------
__device__ float g_gram[(size_t)BB * NN * NN];      // scores: 2*inner - xx[col]
__device__ __nv_bfloat16 g_xhi[BB * NN * CC];       // (B,N,64) bf16 hi, row-major
__device__ __nv_bfloat16 g_xlo[BB * NN * CC];       // bf16 lo residual
__device__ float g_qT[BB * NN * CC];
__device__ float g_kT[BB * NN * CC];
__device__ float g_vT[BB * NN * CC];
__device__ float g_xx[BB * NN];
__device__ int   g_idx[BB * NN * KK];
__device__ float g_attnT[BB * NN * CC];
__device__ float g_y1T[BB * NN * CC];
__device__ float g_y2T[BB * NN * CC];
__device__ float g_p1s[64 * 256], g_p1ss[64 * 256];
__device__ float g_p2s[64 * 256], g_p2ss[64 * 256];
__device__ float g_sc1[64], g_sh1[64], g_sc2[64], g_sh2[64];

// ---------------- helpers ----------------
__device__ __forceinline__ uint32_t smem_u32(const void* p) {
    uint32_t a;
    asm("{ .reg .u64 t; cvta.to.shared.u64 t, %1; cvt.u32.u64 %0, t; }" : "=r"(a) : "l"(p));
    return a;
}
#define SW128(off) ((off) ^ (((off) >> 3) & 0x70))

// ---------------- K1: projections + norms + bf16 hi/lo split ----------------
__global__ void proj_kernel(const float* __restrict__ x,
                            const float* __restrict__ Wq,
                            const float* __restrict__ Wk,
                            const float* __restrict__ Wv) {
    __shared__ float xs[64][33];
    __shared__ float os[32][65];
    int b = blockIdx.y;
    int n0 = blockIdx.x * 32;
    int t = threadIdx.x;
    const float* xb = x + (size_t)b * CC * NN;

    #pragma unroll
    for (int i = 0; i < 8; i++) {
        int e = t + i * 256;
        int c = e >> 5, j = e & 31;
        xs[c][j] = xb[c * NN + n0 + j];
    }
    __syncthreads();

    if (t < 32) {
        float s = 0.f;
        #pragma unroll
        for (int c = 0; c < 64; c++) { float v = xs[c][t]; s += v * v; }
        g_xx[b * NN + n0 + t] = s;
    }

    #pragma unroll
    for (int i = 0; i < 4; i++) {
        int e = t + i * 256;
        int p = e >> 5;
        int cp = e & 31;
        float v0 = xs[cp * 2][p], v1 = xs[cp * 2 + 1][p];
        __nv_bfloat16 h0 = __float2bfloat16(v0);
        __nv_bfloat16 h1 = __float2bfloat16(v1);
        __nv_bfloat16 l0 = __float2bfloat16(v0 - __bfloat162float(h0));
        __nv_bfloat16 l1 = __float2bfloat16(v1 - __bfloat162float(h1));
        size_t off = ((size_t)(b * NN + n0 + p)) * 64 + cp * 2;
        __nv_bfloat162 hh; hh.x = h0; hh.y = h1;
        __nv_bfloat162 ll; ll.x = l0; ll.y = l1;
        *(__nv_bfloat162*)(g_xhi + off) = hh;
        *(__nv_bfloat162*)(g_xlo + off) = ll;
    }

    int lane = t & 31;
    int w = t >> 5;
    const float* Ws[3] = {Wq, Wk, Wv};
    float* Os[3] = {g_qT, g_kT, g_vT};

    #pragma unroll
    for (int mtx = 0; mtx < 3; mtx++) {
        const float* W = Ws[mtx];
        #pragma unroll
        for (int p = 0; p < 8; p++) {
            int o = p * 8 + w;
            float s = 0.f;
            #pragma unroll
            for (int c = 0; c < 64; c++) s += W[o * 64 + c] * xs[c][lane];
            os[lane][o] = s;
        }
        __syncthreads();
        float* Ob = Os[mtx] + ((size_t)(b * NN + n0)) * 64;
        #pragma unroll
        for (int q = 0; q < 8; q++) {
            int e = t + q * 256;
            int pt = e >> 6, o = e & 63;
            Ob[pt * 64 + o] = os[pt][o];
        }
        __syncthreads();
    }
}

// ---------------- K2: Gram via mma.sync bf16 split (HMMA) ----------------
#define GSM_XX 0
#define GSM_AHI 512
#define GSM_ALO (512 + 16384)
#define GSM_BHI (512 + 32768)
#define GSM_BLO (512 + 49152)
#define GRAM_SMEM (512 + 65536)

__global__ void __launch_bounds__(256) gram_hmma_kernel() {
    extern __shared__ char smem[];
    float* xxs = (float*)(smem + GSM_XX);
    uint32_t sb = smem_u32(smem);
    int t = threadIdx.x, lane = t & 31, w = t >> 5;
    int b = blockIdx.z;
    int m0 = blockIdx.x * 128;
    int n0 = blockIdx.y * 128;

    if (t < 128) xxs[t] = g_xx[b * NN + n0 + t];

    {
        int row = t >> 1, half = t & 1;
        const uint4* gAh = (const uint4*)(g_xhi + ((size_t)(b * NN + m0 + row)) * 64) + half * 4;
        const uint4* gAl = (const uint4*)(g_xlo + ((size_t)(b * NN + m0 + row)) * 64) + half * 4;
        const uint4* gBh = (const uint4*)(g_xhi + ((size_t)(b * NN + n0 + row)) * 64) + half * 4;
        const uint4* gBl = (const uint4*)(g_xlo + ((size_t)(b * NN + n0 + row)) * 64) + half * 4;
        #pragma unroll
        for (int i = 0; i < 4; i++) {
            uint32_t off = SW128((uint32_t)(row * 128 + (half * 4 + i) * 16));
            *(uint4*)(smem + GSM_AHI + off) = gAh[i];
            *(uint4*)(smem + GSM_ALO + off) = gAl[i];
            *(uint4*)(smem + GSM_BHI + off) = gBh[i];
            *(uint4*)(smem + GSM_BLO + off) = gBl[i];
        }
    }
    __syncthreads();

    int wm = (w >> 1) * 32;
    int wn = (w & 1) * 64;

    float acc[2][8][4];
    #pragma unroll
    for (int mi = 0; mi < 2; mi++)
        #pragma unroll
        for (int ni = 0; ni < 8; ni++)
            #pragma unroll
            for (int j = 0; j < 4; j++) acc[mi][ni][j] = 0.f;

    int a_r = ((lane >> 3) & 1) * 8 + (lane & 7);
    int a_c = (lane >> 4) * 16;
    int b_r = (lane >> 4) * 8 + (lane & 7);
    int b_c = ((lane >> 3) & 1) * 16;

    #pragma unroll
    for (int pass = 0; pass < 3; pass++) {
        uint32_t abase = sb + (pass == 2 ? GSM_ALO : GSM_AHI);
        uint32_t bbase = sb + (pass == 1 ? GSM_BLO : GSM_BHI);
        #pragma unroll
        for (int kk = 0; kk < 4; kk++) {
            uint32_t a_frag[2][4];
            #pragma unroll
            for (int mi = 0; mi < 2; mi++) {
                int arow = wm + mi * 16 + a_r;
                uint32_t addr = abase + SW128((uint32_t)(arow * 128 + kk * 32 + a_c));
                asm volatile("ldmatrix.sync.aligned.m8n8.x4.shared.b16 {%0,%1,%2,%3}, [%4];"
                    : "=r"(a_frag[mi][0]), "=r"(a_frag[mi][1]),
                      "=r"(a_frag[mi][2]), "=r"(a_frag[mi][3])
                    : "r"(addr));
            }
            uint32_t b_frag[8][2];
            #pragma unroll
            for (int nb = 0; nb < 4; nb++) {
                int brow = wn + nb * 16 + b_r;
                uint32_t addr = bbase + SW128((uint32_t)(brow * 128 + kk * 32 + b_c));
                uint32_t r0, r1, r2, r3;
                asm volatile("ldmatrix.sync.aligned.m8n8.x4.shared.b16 {%0,%1,%2,%3}, [%4];"
                    : "=r"(r0), "=r"(r1), "=r"(r2), "=r"(r3) : "r"(addr));
                b_frag[nb * 2][0] = r0;     b_frag[nb * 2][1] = r1;
                b_frag[nb * 2 + 1][0] = r2; b_frag[nb * 2 + 1][1] = r3;
            }
            #pragma unroll
            for (int mi = 0; mi < 2; mi++)
                #pragma unroll
                for (int ni = 0; ni < 8; ni++)
                    asm volatile(
                        "mma.sync.aligned.m16n8k16.row.col.f32.bf16.bf16.f32 "
                        "{%0,%1,%2,%3}, {%4,%5,%6,%7}, {%8,%9}, {%0,%1,%2,%3};"
                        : "+f"(acc[mi][ni][0]), "+f"(acc[mi][ni][1]),
                          "+f"(acc[mi][ni][2]), "+f"(acc[mi][ni][3])
                        : "r"(a_frag[mi][0]), "r"(a_frag[mi][1]),
                          "r"(a_frag[mi][2]), "r"(a_frag[mi][3]),
                          "r"(b_frag[ni][0]), "r"(b_frag[ni][1]));
        }
    }

    int qrow = lane >> 2, qcol = (lane & 3) * 2;
    #pragma unroll
    for (int mi = 0; mi < 2; mi++) {
        int row0 = m0 + wm + mi * 16 + qrow;
        float* drow = g_gram + ((size_t)(b * NN + row0)) * NN + n0;
        #pragma unroll
        for (int ni = 0; ni < 8; ni++) {
            int col = wn + ni * 8 + qcol;
            float xx0 = xxs[col], xx1 = xxs[col + 1];
            *(float2*)(drow + col) =
                make_float2(2.f * acc[mi][ni][0] - xx0, 2.f * acc[mi][ni][1] - xx1);
            *(float2*)(drow + 8 * (size_t)NN + col) =
                make_float2(2.f * acc[mi][ni][2] - xx0, 2.f * acc[mi][ni][3] - xx1);
        }
    }
}

// ---------------- K3: top-32 per row (warp per row, per-lane top-4 buffer) ----
__device__ __forceinline__ int colof(int lane, int i) {
    return ((i >> 2) << 7) + (lane << 2) + (i & 3);
}

__global__ void topk_kernel() {
    int t = threadIdx.x;
    int lane = t & 31;
    int row = blockIdx.x * 8 + (t >> 5);
    const float* srow = g_gram + (size_t)row * NN;

    float vals[64];
    #pragma unroll
    for (int j = 0; j < 16; j++) {
        float4 s4 = *(const float4*)&srow[j * 128 + lane * 4];
        vals[j * 4 + 0] = s4.x; vals[j * 4 + 1] = s4.y;
        vals[j * 4 + 2] = s4.z; vals[j * 4 + 3] = s4.w;
    }

    float b0 = -FLT_MAX, b1 = -FLT_MAX, b2 = -FLT_MAX, b3 = -FLT_MAX;
    int i0 = 0, i1 = 0, i2 = 0, i3 = 0;
    #pragma unroll
    for (int i = 0; i < 64; i++) {
        float v = vals[i];
        bool g0 = v > b0, g1 = v > b1, g2 = v > b2, g3 = v > b3;
        b3 = g2 ? b2 : (g3 ? v : b3);  i3 = g2 ? i2 : (g3 ? i : i3);
        b2 = g1 ? b1 : (g2 ? v : b2);  i2 = g1 ? i1 : (g2 ? i : i2);
        b1 = g0 ? b0 : (g1 ? v : b1);  i1 = g0 ? i0 : (g1 ? i : i1);
        b0 = g0 ? v  : b0;             i0 = g0 ? i  : i0;
    }

    unsigned long long dead = 0ull;
    int cnt = 4;
    int* orow = g_idx + row * 32;

    #pragma unroll 1
    for (int r = 0; r < 32; r++) {
        float v = b0;
        int gi = colof(lane, i0);
        #pragma unroll
        for (int off = 16; off; off >>= 1) {
            float ov = __shfl_xor_sync(0xffffffffu, v, off);
            int oi = __shfl_xor_sync(0xffffffffu, gi, off);
            if (ov > v || (ov == v && oi < gi)) { v = ov; gi = oi; }
        }
        if (lane == 0) orow[r] = gi;
        if (colof(lane, i0) == gi) {
            dead |= (1ull << i0);
            b0 = b1; i0 = i1; b1 = b2; i1 = i2; b2 = b3; i2 = i3; b3 = -FLT_MAX;
            if (--cnt == 0) {
                b0 = b1 = b2 = b3 = -FLT_MAX;
                #pragma unroll
                for (int i = 0; i < 64; i++) {
                    float v2 = ((dead >> i) & 1ull) ? -FLT_MAX : vals[i];
                    bool g0 = v2 > b0, g1 = v2 > b1, g2 = v2 > b2, g3 = v2 > b3;
                    b3 = g2 ? b2 : (g3 ? v2 : b3);  i3 = g2 ? i2 : (g3 ? i : i3);
                    b2 = g1 ? b1 : (g2 ? v2 : b2);  i2 = g1 ? i1 : (g2 ? i : i2);
                    b1 = g0 ? b0 : (g1 ? v2 : b1);  i1 = g0 ? i0 : (g1 ? i : i1);
                    b0 = g0 ? v2 : b0;              i0 = g0 ? i  : i0;
                }
                cnt = 4;
            }
        }
    }
}

// ---------------- K4: attention (warp/point, cooperative energy reduction) --
__global__ void __launch_bounds__(256) attn_kernel() {
    __shared__ float sq[8][64], sk[8][64], sv[8][64];
    __shared__ float sa[8][32][9];
    __shared__ int smi[8][32];
    int t = threadIdx.x, lane = t & 31, wl = t >> 5;
    int pt = blockIdx.x * 8 + wl;
    int b = pt >> 11;
    size_t base = (size_t)pt * 64;

    sq[wl][lane] = g_qT[base + lane];  sq[wl][lane + 32] = g_qT[base + lane + 32];
    sk[wl][lane] = g_kT[base + lane];  sk[wl][lane + 32] = g_kT[base + lane + 32];
    sv[wl][lane] = g_vT[base + lane];  sv[wl][lane + 32] = g_vT[base + lane + 32];
    smi[wl][lane] = g_idx[pt * 32 + lane];
    __syncwarp();

    int c0 = lane * 2;
    int myh = lane >> 2;
    float q0 = sq[wl][c0], q1 = sq[wl][c0 + 1];
    float k0 = sk[wl][c0], k1 = sk[wl][c0 + 1];
    bool writer = (lane & 3) == 0;

    #pragma unroll 4
    for (int k = 0; k < 32; k++) {
        int mm = smi[wl][k];
        float2 kv = ((const float2*)(g_kT + ((size_t)(b * NN + mm)) * 64))[lane];
        float p = q0 * (kv.x - k0) + q1 * (kv.y - k1);
        p += __shfl_xor_sync(0xffffffffu, p, 1);
        p += __shfl_xor_sync(0xffffffffu, p, 2);
        if (writer) sa[wl][k][myh] = p;
    }
    __syncwarp();

    const float scale = 0.3535533905932738f;
    float e[8];
    #pragma unroll
    for (int h = 0; h < 8; h++) e[h] = sa[wl][lane][h] * scale;
    #pragma unroll
    for (int h = 0; h < 8; h++) {
        float mx = e[h];
        #pragma unroll
        for (int off = 16; off; off >>= 1)
            mx = fmaxf(mx, __shfl_xor_sync(0xffffffffu, mx, off));
        float p = __expf(e[h] - mx);
        float s = p;
        #pragma unroll
        for (int off = 16; off; off >>= 1)
            s += __shfl_xor_sync(0xffffffffu, s, off);
        sa[wl][lane][h] = p / s;
    }
    __syncwarp();

    int c1 = lane, c2 = lane + 32;
    int h1 = lane >> 3, h2 = h1 + 4;
    float svc1 = sv[wl][c1], svc2 = sv[wl][c2];
    float acc1 = 0.f, acc2 = 0.f;
    #pragma unroll 8
    for (int k = 0; k < 32; k++) {
        int mm = smi[wl][k];
        const float* vrow = g_vT + ((size_t)(b * NN + mm)) * 64;
        acc1 += sa[wl][k][h1] * (vrow[c1] - svc1);
        acc2 += sa[wl][k][h2] * (vrow[c2] - svc2);
    }
    g_attnT[base + c1] = acc1;
    g_attnT[base + c2] = acc2;
}

// ---------------- K5: y1 = x + attn (tile transpose); partial BN1 stats -----
__global__ void __launch_bounds__(256) bn1_kernel(const float* __restrict__ x) {
    __shared__ float xt[64][65];
    __shared__ float red[4][64], redss[4][64];
    int t = threadIdx.x;
    int b = blockIdx.y;
    int n0 = blockIdx.x * 64;
    const float* xb = x + (size_t)b * CC * NN;

    #pragma unroll
    for (int i = 0; i < 16; i++) {
        int e = t + i * 256;
        int c = e >> 6, n = e & 63;
        xt[c][n] = xb[c * NN + n0 + n];
    }
    __syncthreads();

    int ch = t & 63, pg = t >> 6;
    float lsum = 0.f, lss = 0.f;
    #pragma unroll
    for (int i = 0; i < 16; i++) {
        int p = pg + i * 4;
        size_t row = ((size_t)(b * NN + n0 + p)) * 64;
        float v = xt[ch][p] + g_attnT[row + ch];
        g_y1T[row + ch] = v;
        lsum += v; lss += v * v;
    }
    red[pg][ch] = lsum; redss[pg][ch] = lss;
    __syncthreads();
    if (t < 64) {
        float S = red[0][t] + red[1][t] + red[2][t] + red[3][t];
        float SS = redss[0][t] + redss[1][t] + redss[2][t] + redss[3][t];
        int bi = b * 32 + blockIdx.x;
        g_p1s[t * 256 + bi] = S;
        g_p1ss[t * 256 + bi] = SS;
    }
}

// 256 threads: 4 per channel, each sums 64 slots, 2-step shfl reduce.
__global__ void finalize1_kernel(const float* __restrict__ gamma,
                                 const float* __restrict__ beta) {
    int t = threadIdx.x;
    int c = t >> 2, q = t & 3;
    float S = 0, SS = 0;
    #pragma unroll 4
    for (int i = q; i < 256; i += 4) { S += g_p1s[c * 256 + i]; SS += g_p1ss[c * 256 + i]; }
    S += __shfl_xor_sync(0xffffffffu, S, 1);  SS += __shfl_xor_sync(0xffffffffu, SS, 1);
    S += __shfl_xor_sync(0xffffffffu, S, 2);  SS += __shfl_xor_sync(0xffffffffu, SS, 2);
    if (q == 0) {
        float mean = S * (1.f / 16384.f);
        float var = SS * (1.f / 16384.f) - mean * mean;
        float r = rsqrtf(var + 1e-5f);
        float sc = gamma[c] * r;
        g_sc1[c] = sc;
        g_sh1[c] = beta[c] - mean * sc;
    }
}

// ---------------- K6: fused FFN, warp-per-point (no block syncs in loop) ----
// grid (32, 8), block 256 = 8 warps, 64 points/block, 8 points/warp.
// smem: W1s[c][o] (32KB), W2sT[j][c] (32KB), per-warp x1/h buffers, reduce.
#define FF_W1 0                          // [64][128]
#define FF_W2 (64 * 128)                 // [128][64]
#define FF_XB (FF_W2 + 128 * 64)         // [8][64]
#define FF_HB (FF_XB + 8 * 64)           // [8][128]
#define FF_RS (FF_HB + 8 * 128)          // [8][64]
#define FF_RSS (FF_RS + 8 * 64)          // [8][64]
#define FF_SC (FF_RSS + 8 * 64)          // [64]
#define FF_SH (FF_SC + 64)               // [64]
#define FFN_SMEM ((FF_SH + 64) * 4)

__global__ void __launch_bounds__(256) ffn_fused_kernel(const float* __restrict__ W1,
                                                        const float* __restrict__ W2) {
    extern __shared__ float fsm[];
    float* W1s  = fsm + FF_W1;
    float* W2sT = fsm + FF_W2;
    int t = threadIdx.x, lane = t & 31, wl = t >> 5;
    float* xb = fsm + FF_XB + wl * 64;
    float* hb = fsm + FF_HB + wl * 128;

    #pragma unroll 8
    for (int i = 0; i < 32; i++) {
        int e = t + i * 256;                 // 0..8191
        W1s[(e & 63) * 128 + (e >> 6)] = W1[e];   // W1[o*64+c] -> W1s[c][o]
        W2sT[(e & 127) * 64 + (e >> 7)] = W2[e];  // W2[c*128+j] -> W2sT[j][c]
    }
    if (t < 64) { fsm[FF_SC + t] = g_sc1[t]; fsm[FF_SH + t] = g_sh1[t]; }
    int b = blockIdx.y;
    int p0 = blockIdx.x * 64 + wl * 8;       // this warp's first point
    __syncthreads();

    float2 scv = *(const float2*)&fsm[FF_SC + lane * 2];
    float2 shv = *(const float2*)&fsm[FF_SH + lane * 2];
    const float4* W1s4 = (const float4*)W1s;
    const float2* W2sT2 = (const float2*)W2sT;

    float s0 = 0.f, ss0 = 0.f, s1 = 0.f, ss1 = 0.f;   // stats for ch 2l, 2l+1

    #pragma unroll 1
    for (int p = 0; p < 8; p++) {
        size_t pt = (size_t)(b * NN + p0 + p);
        float2 y1 = ((const float2*)(g_y1T + pt * 64))[lane];
        float x1a = y1.x * scv.x + shv.x;
        float x1b = y1.y * scv.y + shv.y;
        *(float2*)&xb[lane * 2] = make_float2(x1a, x1b);
        __syncwarp();

        // phase 1: h[4l..4l+3] = leaky(W1[o,:] . x1)
        float4 a = make_float4(0.f, 0.f, 0.f, 0.f);
        #pragma unroll
        for (int c = 0; c < 64; c++) {
            float xc = xb[c];
            float4 w = W1s4[c * 32 + lane];
            a.x += w.x * xc; a.y += w.y * xc; a.z += w.z * xc; a.w += w.w * xc;
        }
        a.x = a.x > 0.f ? a.x : 0.2f * a.x;
        a.y = a.y > 0.f ? a.y : 0.2f * a.y;
        a.z = a.z > 0.f ? a.z : 0.2f * a.z;
        a.w = a.w > 0.f ? a.w : 0.2f * a.w;
        *(float4*)&hb[lane * 4] = a;
        __syncwarp();

        // phase 2: y2[2l,2l+1] = x1 + W2[c,:] . h
        float acc0 = 0.f, acc1 = 0.f;
        #pragma unroll
        for (int j = 0; j < 128; j++) {
            float hj = hb[j];
            float2 w = W2sT2[j * 32 + lane];
            acc0 += w.x * hj; acc1 += w.y * hj;
        }
        float y20 = x1a + acc0, y21 = x1b + acc1;
        ((float2*)(g_y2T + pt * 64))[lane] = make_float2(y20, y21);
        s0 += y20; ss0 += y20 * y20;
        s1 += y21; ss1 += y21 * y21;
        __syncwarp();
    }

    // block-reduce stats across 8 warps
    float* rs = fsm + FF_RS + wl * 64;
    float* rss = fsm + FF_RSS + wl * 64;
    rs[lane * 2] = s0;  rs[lane * 2 + 1] = s1;
    rss[lane * 2] = ss0; rss[lane * 2 + 1] = ss1;
    __syncthreads();
    if (t < 64) {
        float S = 0, SS = 0;
        #pragma unroll
        for (int w = 0; w < 8; w++) {
            S += fsm[FF_RS + w * 64 + t];
            SS += fsm[FF_RSS + w * 64 + t];
        }
        int bi = b * 32 + blockIdx.x;
        g_p2s[t * 256 + bi] = S;
        g_p2ss[t * 256 + bi] = SS;
    }
}

__global__ void finalize2_kernel(const float* __restrict__ gamma,
                                 const float* __restrict__ beta) {
    int t = threadIdx.x;
    int c = t >> 2, q = t & 3;
    float S = 0, SS = 0;
    #pragma unroll 4
    for (int i = q; i < 256; i += 4) { S += g_p2s[c * 256 + i]; SS += g_p2ss[c * 256 + i]; }
    S += __shfl_xor_sync(0xffffffffu, S, 1);  SS += __shfl_xor_sync(0xffffffffu, SS, 1);
    S += __shfl_xor_sync(0xffffffffu, S, 2);  SS += __shfl_xor_sync(0xffffffffu, SS, 2);
    if (q == 0) {
        float mean = S * (1.f / 16384.f);
        float var = SS * (1.f / 16384.f) - mean * mean;
        float r = rsqrtf(var + 1e-5f);
        float sc = gamma[c] * r;
        g_sc2[c] = sc;
        g_sh2[c] = beta[c] - mean * sc;
    }
}

// ---------------- K7: apply BN2 -> output (B,C,N), tile transpose ----------
__global__ void __launch_bounds__(256) apply_bn2_kernel(float* __restrict__ out) {
    __shared__ float yt[64][65];
    int t = threadIdx.x;
    int b = blockIdx.y;
    int n0 = blockIdx.x * 64;

    #pragma unroll
    for (int i = 0; i < 16; i++) {
        int e = t + i * 256;
        int p = e >> 6, ch = e & 63;
        yt[ch][p] = g_y2T[((size_t)(b * NN + n0 + p)) * 64 + ch];
    }
    __syncthreads();

    float* ob = out + (size_t)b * CC * NN;
    #pragma unroll
    for (int i = 0; i < 16; i++) {
        int e = t + i * 256;
        int c = e >> 6, n = e & 63;
        ob[c * NN + n0 + n] = yt[c][n] * g_sc2[c] + g_sh2[c];
    }
}

// ---------------- launch ----------------
extern "C" void kernel_launch(void* const* d_in, const int* in_sizes, int n_in,
                              void* d_out, int out_size) {
    const float* x  = (const float*)d_in[0];
    const float* Wq = (const float*)d_in[1];
    const float* Wk = (const float*)d_in[2];
    const float* Wv = (const float*)d_in[3];
    const float* W1 = (const float*)d_in[4];
    const float* W2 = (const float*)d_in[5];
    const float* g1 = (const float*)d_in[6];
    const float* b1 = (const float*)d_in[7];
    const float* g2 = (const float*)d_in[8];
    const float* b2 = (const float*)d_in[9];
    float* out = (float*)d_out;

    cudaFuncSetAttribute(gram_hmma_kernel,
                         cudaFuncAttributeMaxDynamicSharedMemorySize, GRAM_SMEM);
    cudaFuncSetAttribute(ffn_fused_kernel,
                         cudaFuncAttributeMaxDynamicSharedMemorySize, FFN_SMEM);

    proj_kernel<<<dim3(64, 8), 256>>>(x, Wq, Wk, Wv);
    gram_hmma_kernel<<<dim3(16, 16, 8), 256, GRAM_SMEM>>>();
    topk_kernel<<<2048, 256>>>();
    attn_kernel<<<2048, 256>>>();
    bn1_kernel<<<dim3(32, 8), 256>>>(x);
    finalize1_kernel<<<1, 256>>>(g1, b1);
    ffn_fused_kernel<<<dim3(32, 8), 256, FFN_SMEM>>>(W1, W2);
    finalize2_kernel<<<1, 256>>>(g2, b2);
    apply_bn2_kernel<<<dim3(32, 8), 256>>>(out);
}